// round 8
// baseline (speedup 1.0000x reference)
#include <cuda_runtime.h>
#include <cstdint>
#include <math.h>

#define NIMG 16
#define NPROP 16384
#define NGT 128
#define M_TOT 16512           // NPROP + NGT
#define KPOS 128
#define KNEG 384
#define NSAMP 512
#define CAP 2048              // per (img, cat) candidate capacity
#define CAPF 4096             // fallback buffer
#define TNEG 7864320u         // 2^23 - 2^19 : neg score window

typedef unsigned long long ull;

// ---------------- scratch (zero-initialized at module load) ----------------
__device__ unsigned g_rec[NIMG * M_TOT];     // (u23<<1)|is_pos  (fallback only)
__device__ int g_labcl[NIMG * M_TOT];        // label|(cl<<8)    (positives)
__device__ ull g_cand[NIMG * 2 * CAP];
__device__ int g_ccnt[NIMG * 2];             // reset by select at end of each run

// ---------------- threefry2x32 (jax partitionable path) ----------------
__device__ __forceinline__ unsigned rscore_u(unsigned f) {
    unsigned k0 = 0u, k1 = 42u;
    unsigned ks2 = k0 ^ k1 ^ 0x1BD11BDAu;
    unsigned x0 = 0u, x1 = f;
    x0 += k0; x1 += k1;
#define TF_R(r) { x0 += x1; x1 = (x1 << (r)) | (x1 >> (32 - (r))); x1 ^= x0; }
    TF_R(13) TF_R(15) TF_R(26) TF_R(6)
    x0 += k1; x1 += ks2 + 1u;
    TF_R(17) TF_R(29) TF_R(16) TF_R(24)
    x0 += ks2; x1 += k0 + 2u;
    TF_R(13) TF_R(15) TF_R(26) TF_R(6)
    x0 += k0; x1 += k1 + 3u;
    TF_R(17) TF_R(29) TF_R(16) TF_R(24)
    x0 += k1; x1 += ks2 + 4u;
    TF_R(13) TF_R(15) TF_R(26) TF_R(6)
    x0 += ks2; x1 += k0 + 5u;
#undef TF_R
    return (x0 ^ x1) >> 9;   // 23-bit uniform; score = u * 2^-23 (monotone)
}

// ---------------- kernel A: R6 LUT-windowed screen + redo + append ----------------
__global__ void __launch_bounds__(256) prep_kernel(
        const float4* __restrict__ proposals,
        const float4* __restrict__ gt_boxes,
        const int* __restrict__ gt_labels) {
    __shared__ float4 s_gt[NGT];     // original order (redo + GT-proposal loads)
    __shared__ float  s_area[NGT];   // full areas (redo)
    __shared__ int    s_lab[NGT];
    __shared__ float4 s_sgt[NGT];    // sorted by x1
    __shared__ float  s_sa3[NGT];    // area/3, sorted
    __shared__ int    s_lutlo[256];
    __shared__ int    s_luthi[256];
    __shared__ int    s_flag[1024];
    __shared__ int    s_nflag;

    const int i = blockIdx.y;
    const int t = threadIdx.x;
    const int lane = t & 31;
    if (t == 0) s_nflag = 0;
    if (t < NGT) {
        float4 g = gt_boxes[i * NGT + t];
        s_gt[t] = g;
        s_area[t] = __fmul_rn(__fsub_rn(g.z, g.x), __fsub_rn(g.w, g.y));
        s_lab[t] = gt_labels[i * NGT + t];
    }
    __syncthreads();
    if (t < NGT) {
        float gx = s_gt[t].x;
        int rank = 0;
        for (int j = 0; j < NGT; j++) {
            float oj = s_gt[j].x;
            rank += (oj < gx) || (oj == gx && j < t);
        }
        s_sgt[rank] = s_gt[t];
        s_sa3[rank] = s_area[t] * (1.0f / 3.0f);
    }
    __syncthreads();
    {   // bucket -> sorted-index LUT (conservative: superset window)
        const float vlo = t * (801.0f / 256.0f);
        const float vhi = (t + 1) * (801.0f / 256.0f);
        int clo = 0, chi = 0;
        for (int j = 0; j < NGT; j++) {
            float x = s_sgt[j].x;          // uniform j -> LDS broadcast
            clo += (x < vlo);
            chi += (x <= vhi);
        }
        s_lutlo[t] = clo;
        s_luthi[t] = chi;
    }
    __syncthreads();

    const int gi = i * M_TOT;
    const int mb = blockIdx.x * 1024 + t * 4;
    unsigned rv[4] = {0u, 0u, 0u, 0u};
    unsigned u4[4] = {0u, 0u, 0u, 0u};
    bool fl4[4] = {false, false, false, false};

    #pragma unroll
    for (int q = 0; q < 4; q++) {
        const int m = mb + q;
        if (m >= M_TOT) continue;
        float4 p = (m < NPROP) ? proposals[(size_t)i * NPROP + m] : s_gt[m - NPROP];
        const float ab3 = __fmul_rn(__fmul_rn(__fsub_rn(p.z, p.x), __fsub_rn(p.w, p.y)),
                                    (1.0f / 3.0f));
        int lb = (int)((p.x - 202.0f) * (256.0f / 801.0f));
        lb = min(max(lb, 0), 255);
        int hb = (int)(p.z * (256.0f / 801.0f));
        hb = min(max(hb, 0), 255);
        const int lo = s_lutlo[lb];
        const int hi = s_luthi[hb];

        // flag iff possibly max-IoU >= 0.5:  inter - (area_g+area_b)/3 >= -1.0
        float acc = -1e30f;
        for (int j = lo; j < hi; j++) {
            float4 g = s_sgt[j];
            float wx = __fsub_rn(fminf(g.z, p.z), fmaxf(g.x, p.x));
            float hy = __fsub_rn(fminf(g.w, p.w), fmaxf(g.y, p.y));
            float inter = __fmul_rn(fmaxf(wx, 0.0f), fmaxf(hy, 0.0f));
            acc = fmaxf(acc, __fsub_rn(inter, __fadd_rn(s_sa3[j], ab3)));
        }
        unsigned u = rscore_u((unsigned)(gi + m));
        u4[q] = u;
        rv[q] = u << 1;                                   // default: negative
        if (acc >= -1.0f) { int pp = atomicAdd(&s_nflag, 1); s_flag[pp] = m; fl4[q] = true; }
    }
    if (mb + 3 < M_TOT) {
        *reinterpret_cast<uint4*>(&g_rec[gi + mb]) = make_uint4(rv[0], rv[1], rv[2], rv[3]);
    } else {
        for (int q = 0; q < 4; q++) if (mb + q < M_TOT) g_rec[gi + mb + q] = rv[q];
    }

    // negative candidate append (unflagged, windowed) — warp-aggregated
    #pragma unroll
    for (int q = 0; q < 4; q++) {
        bool pq = (mb + q < M_TOT) && !fl4[q] && (u4[q] >= TNEG);
        unsigned msk = __ballot_sync(0xFFFFFFFFu, pq);
        if (msk) {
            int leader = __ffs(msk) - 1;
            int base = 0;
            if (lane == leader) base = atomicAdd(&g_ccnt[i * 2 + 1], __popc(msk));
            base = __shfl_sync(0xFFFFFFFFu, base, leader);
            if (pq) {
                int pos = base + __popc(msk & ((1u << lane) - 1u));
                if (pos < CAP)
                    g_cand[(i * 2 + 1) * CAP + pos] =
                        ((ull)u4[q] << 32) | (unsigned)(~(unsigned)(mb + q));
            }
        }
    }
    __syncthreads();

    // ---- exact redo: one warp per flagged proposal (validated path) ----
    const int nf = s_nflag;
    const int wid = t >> 5;
    for (int e = wid; e < nf; e += 8) {
        const int m = s_flag[e];
        float4 p = (m < NPROP) ? proposals[(size_t)i * NPROP + m] : s_gt[m - NPROP];
        const float ab = __fmul_rn(__fsub_rn(p.z, p.x), __fsub_rn(p.w, p.y));

        float bi, bd; int bj;
        {
            float4 g = s_gt[lane];
            float wx = __fsub_rn(fminf(g.z, p.z), fmaxf(g.x, p.x));
            float hy = __fsub_rn(fminf(g.w, p.w), fmaxf(g.y, p.y));
            bi = __fmul_rn(fmaxf(wx, 0.0f), fmaxf(hy, 0.0f));
            bd = __fsub_rn(__fadd_rn(s_area[lane], ab), bi);
            bj = lane;
        }
        #pragma unroll
        for (int kk = 1; kk < 4; kk++) {
            int j = lane + kk * 32;
            float4 g = s_gt[j];
            float wx = __fsub_rn(fminf(g.z, p.z), fmaxf(g.x, p.x));
            float hy = __fsub_rn(fminf(g.w, p.w), fmaxf(g.y, p.y));
            float inter = __fmul_rn(fmaxf(wx, 0.0f), fmaxf(hy, 0.0f));
            float den = __fsub_rn(__fadd_rn(s_area[j], ab), inter);
            float u = __fmul_rn(inter, bd), v = __fmul_rn(bi, den);
            float eu = __fmaf_rn(inter, bd, -u), ev = __fmaf_rn(bi, den, -v);
            if ((u > v) || (u == v && eu > ev)) { bi = inter; bd = den; bj = j; }
        }
        #pragma unroll
        for (int off = 16; off > 0; off >>= 1) {
            float obi = __shfl_xor_sync(0xFFFFFFFFu, bi, off);
            float obd = __shfl_xor_sync(0xFFFFFFFFu, bd, off);
            int   obj = __shfl_xor_sync(0xFFFFFFFFu, bj, off);
            float u = __fmul_rn(obi, bd), v = __fmul_rn(bi, obd);
            float eu = __fmaf_rn(obi, bd, -u), ev = __fmaf_rn(bi, obd, -v);
            bool gt = (u > v) || (u == v && eu > ev);
            bool eq = (u == v) && (eu == ev);
            if (gt || (eq && obj < bj)) { bi = obi; bd = obd; bj = obj; }
        }
        if (lane == 0) {
            bool pos = __fdiv_rn(bi, bd) >= 0.5f;     // bit-exact threshold
            unsigned u = rscore_u((unsigned)(gi + m));
            g_rec[gi + m] = (u << 1) | (pos ? 1u : 0u);
            if (pos) {
                g_labcl[gi + m] = s_lab[bj] | (bj << 8);
                int p2 = atomicAdd(&g_ccnt[i * 2 + 0], 1);
                if (p2 < CAP)
                    g_cand[(i * 2 + 0) * CAP + p2] = ((ull)u << 32) | (unsigned)(~(unsigned)m);
            } else if (u >= TNEG) {
                int p2 = atomicAdd(&g_ccnt[i * 2 + 1], 1);
                if (p2 < CAP)
                    g_cand[(i * 2 + 1) * CAP + p2] = ((ull)u << 32) | (unsigned)(~(unsigned)m);
            }
        }
    }
}

// ---------------- kernel B: candidate rank-sort + encode + counter reset ----------------
__global__ void __launch_bounds__(1024) select_kernel(
        const float4* __restrict__ proposals,
        const float4* __restrict__ gt_boxes,
        float* __restrict__ out) {
    __shared__ ull cand[CAPF];
    __shared__ int s_red[32];
    __shared__ int s_bc, s_cc;

    const int i = blockIdx.x;
    const int cat = blockIdx.y;
    const unsigned want = cat ? 0u : 1u;
    const int k = cat ? KNEG : KPOS;
    const int t = threadIdx.x;
    const int lane = t & 31, wid = t >> 5;

    const int cnt = g_ccnt[i * 2 + cat];
    int CC;
    if (cnt >= k && cnt <= CAP) {
        for (int c = t; c < cnt; c += 1024)
            cand[c] = g_cand[(i * 2 + cat) * CAP + c];
        CC = cnt;
        __syncthreads();
    } else {
        // exact fallback over g_rec (statistically never taken)
        const unsigned* __restrict__ rec = g_rec + (size_t)i * M_TOT;
        unsigned lo = 0, hi = 8388607u;
        while (lo < hi) {
            unsigned mid = (lo + hi + 1) >> 1;
            int c = 0;
            for (int m = t; m < M_TOT; m += 1024) {
                unsigned r = rec[m];
                c += ((r & 1u) == want && (r >> 1) >= mid);
            }
            #pragma unroll
            for (int o = 16; o > 0; o >>= 1) c += __shfl_xor_sync(0xFFFFFFFFu, c, o);
            if (lane == 0) s_red[wid] = c;
            __syncthreads();
            if (t == 0) { int s = 0; for (int w = 0; w < 32; w++) s += s_red[w]; s_bc = s; }
            __syncthreads();
            if (s_bc >= k) lo = mid; else hi = mid - 1;
            __syncthreads();
        }
        if (t == 0) s_cc = 0;
        __syncthreads();
        for (int m = t; m < M_TOT; m += 1024) {
            unsigned r = rec[m];
            if ((r & 1u) == want && (r >> 1) >= lo) {
                int p = atomicAdd(&s_cc, 1);
                if (p < CAPF)
                    cand[p] = ((ull)(r >> 1) << 32) | (unsigned)(~(unsigned)m);
            }
        }
        __syncthreads();
        CC = min(s_cc, CAPF);
    }

    // rank-counting sort (distinct (u,~m) keys) + fused encode
    for (int c = t; c < CC; c += 1024) {
        const ull mykey = cand[c];
        int rnk = 0;
        for (int j = 0; j < CC; j++) rnk += (cand[j] > mykey);
        if (rnk < k) {
            int m = (int)(~(unsigned)(mykey & 0xFFFFFFFFULL));
            int label = 0, cl = 0;
            if (cat == 0) {
                int labcl = g_labcl[(size_t)i * M_TOT + m];
                label = labcl & 0xFF;
                cl = labcl >> 8;
            }
            float4 p = (m < NPROP) ? proposals[(size_t)i * NPROP + m]
                                   : gt_boxes[i * NGT + (m - NPROP)];
            float4 g = gt_boxes[i * NGT + cl];

            float rw = p.z - p.x, rh = p.w - p.y;
            float rcx = p.x + 0.5f * rw, rcy = p.y + 0.5f * rh;
            float gw = g.z - g.x, gh = g.w - g.y;
            float gcx = g.x + 0.5f * gw, gcy = g.y + 0.5f * gh;

            float t0 = 10.0f * __fdiv_rn(gcx - rcx, rw);
            float t1 = 10.0f * __fdiv_rn(gcy - rcy, rh);
            float t2 = 5.0f * logf(__fdiv_rn(gw, rw));
            float t3 = 5.0f * logf(__fdiv_rn(gh, rh));

            int row = i * NSAMP + (cat ? KPOS : 0) + rnk;
            out[row * 4 + 0] = t0;
            out[row * 4 + 1] = t1;
            out[row * 4 + 2] = t2;
            out[row * 4 + 3] = t3;
            out[NIMG * NSAMP * 4 + row] = (float)label;
            out[NIMG * NSAMP * 4 + NIMG * NSAMP + row] = (float)m;
        }
    }
    __syncthreads();
    if (t == 0) g_ccnt[i * 2 + cat] = 0;   // invariant for next graph replay
}

// ---------------- launch ----------------
extern "C" void kernel_launch(void* const* d_in, const int* in_sizes, int n_in,
                              void* d_out, int out_size) {
    const float4* proposals = (const float4*)d_in[0];
    const float4* gt_boxes  = (const float4*)d_in[1];
    const int*    gt_labels = (const int*)d_in[2];
    float* out = (float*)d_out;

    prep_kernel<<<dim3((M_TOT + 1023) / 1024, NIMG), 256>>>(proposals, gt_boxes, gt_labels);
    select_kernel<<<dim3(NIMG, 2), 1024>>>(proposals, gt_boxes, out);
}

// round 10
// speedup vs baseline: 1.9004x; 1.9004x over previous
#include <cuda_runtime.h>
#include <cstdint>
#include <math.h>

#define NIMG 16
#define NPROP 16384
#define NGT 128
#define M_TOT 16512           // NPROP + NGT
#define KPOS 128
#define KNEG 384
#define NSAMP 512
#define CAP 2048              // per (img, cat) candidate capacity
#define CAP2 1024             // refined candidate capacity
#define NBIN 2048
#define TNEG 7864320u         // 2^23 - 2^19 : neg score window

typedef unsigned long long ull;

// ---------------- scratch (zero-initialized at module load) ----------------
__device__ unsigned g_rec[NIMG * M_TOT];     // (u23<<1)|is_pos  (fallback only)
__device__ int g_labcl[NIMG * M_TOT];        // label|(cl<<8)    (positives)
__device__ ull g_cand[NIMG * 2 * CAP];
__device__ int g_ccnt[NIMG * 2];             // reset by select at end of each run

// ---------------- threefry2x32 (jax partitionable path) ----------------
__device__ __forceinline__ unsigned rscore_u(unsigned f) {
    unsigned k0 = 0u, k1 = 42u;
    unsigned ks2 = k0 ^ k1 ^ 0x1BD11BDAu;
    unsigned x0 = 0u, x1 = f;
    x0 += k0; x1 += k1;
#define TF_R(r) { x0 += x1; x1 = (x1 << (r)) | (x1 >> (32 - (r))); x1 ^= x0; }
    TF_R(13) TF_R(15) TF_R(26) TF_R(6)
    x0 += k1; x1 += ks2 + 1u;
    TF_R(17) TF_R(29) TF_R(16) TF_R(24)
    x0 += ks2; x1 += k0 + 2u;
    TF_R(13) TF_R(15) TF_R(26) TF_R(6)
    x0 += k0; x1 += k1 + 3u;
    TF_R(17) TF_R(29) TF_R(16) TF_R(24)
    x0 += k1; x1 += ks2 + 4u;
    TF_R(13) TF_R(15) TF_R(26) TF_R(6)
    x0 += ks2; x1 += k0 + 5u;
#undef TF_R
    return (x0 ^ x1) >> 9;   // 23-bit uniform; score = u * 2^-23 (monotone)
}

// ---------------- kernel A: LUT-windowed screen + redo + append (unchanged R8) ----------------
__global__ void __launch_bounds__(256) prep_kernel(
        const float4* __restrict__ proposals,
        const float4* __restrict__ gt_boxes,
        const int* __restrict__ gt_labels) {
    __shared__ float4 s_gt[NGT];
    __shared__ float  s_area[NGT];
    __shared__ int    s_lab[NGT];
    __shared__ float4 s_sgt[NGT];
    __shared__ float  s_sa3[NGT];
    __shared__ int    s_lutlo[256];
    __shared__ int    s_luthi[256];
    __shared__ int    s_flag[1024];
    __shared__ int    s_nflag;

    const int i = blockIdx.y;
    const int t = threadIdx.x;
    const int lane = t & 31;
    if (t == 0) s_nflag = 0;
    if (t < NGT) {
        float4 g = gt_boxes[i * NGT + t];
        s_gt[t] = g;
        s_area[t] = __fmul_rn(__fsub_rn(g.z, g.x), __fsub_rn(g.w, g.y));
        s_lab[t] = gt_labels[i * NGT + t];
    }
    __syncthreads();
    if (t < NGT) {
        float gx = s_gt[t].x;
        int rank = 0;
        for (int j = 0; j < NGT; j++) {
            float oj = s_gt[j].x;
            rank += (oj < gx) || (oj == gx && j < t);
        }
        s_sgt[rank] = s_gt[t];
        s_sa3[rank] = s_area[t] * (1.0f / 3.0f);
    }
    __syncthreads();
    {
        const float vlo = t * (801.0f / 256.0f);
        const float vhi = (t + 1) * (801.0f / 256.0f);
        int clo = 0, chi = 0;
        for (int j = 0; j < NGT; j++) {
            float x = s_sgt[j].x;
            clo += (x < vlo);
            chi += (x <= vhi);
        }
        s_lutlo[t] = clo;
        s_luthi[t] = chi;
    }
    __syncthreads();

    const int gi = i * M_TOT;
    const int mb = blockIdx.x * 1024 + t * 4;
    unsigned rv[4] = {0u, 0u, 0u, 0u};
    unsigned u4[4] = {0u, 0u, 0u, 0u};
    bool fl4[4] = {false, false, false, false};

    #pragma unroll
    for (int q = 0; q < 4; q++) {
        const int m = mb + q;
        if (m >= M_TOT) continue;
        float4 p = (m < NPROP) ? proposals[(size_t)i * NPROP + m] : s_gt[m - NPROP];
        const float ab3 = __fmul_rn(__fmul_rn(__fsub_rn(p.z, p.x), __fsub_rn(p.w, p.y)),
                                    (1.0f / 3.0f));
        int lb = (int)((p.x - 202.0f) * (256.0f / 801.0f));
        lb = min(max(lb, 0), 255);
        int hb = (int)(p.z * (256.0f / 801.0f));
        hb = min(max(hb, 0), 255);
        const int lo = s_lutlo[lb];
        const int hi = s_luthi[hb];

        float acc = -1e30f;
        for (int j = lo; j < hi; j++) {
            float4 g = s_sgt[j];
            float wx = __fsub_rn(fminf(g.z, p.z), fmaxf(g.x, p.x));
            float hy = __fsub_rn(fminf(g.w, p.w), fmaxf(g.y, p.y));
            float inter = __fmul_rn(fmaxf(wx, 0.0f), fmaxf(hy, 0.0f));
            acc = fmaxf(acc, __fsub_rn(inter, __fadd_rn(s_sa3[j], ab3)));
        }
        unsigned u = rscore_u((unsigned)(gi + m));
        u4[q] = u;
        rv[q] = u << 1;
        if (acc >= -1.0f) { int pp = atomicAdd(&s_nflag, 1); s_flag[pp] = m; fl4[q] = true; }
    }
    if (mb + 3 < M_TOT) {
        *reinterpret_cast<uint4*>(&g_rec[gi + mb]) = make_uint4(rv[0], rv[1], rv[2], rv[3]);
    } else {
        for (int q = 0; q < 4; q++) if (mb + q < M_TOT) g_rec[gi + mb + q] = rv[q];
    }

    #pragma unroll
    for (int q = 0; q < 4; q++) {
        bool pq = (mb + q < M_TOT) && !fl4[q] && (u4[q] >= TNEG);
        unsigned msk = __ballot_sync(0xFFFFFFFFu, pq);
        if (msk) {
            int leader = __ffs(msk) - 1;
            int base = 0;
            if (lane == leader) base = atomicAdd(&g_ccnt[i * 2 + 1], __popc(msk));
            base = __shfl_sync(0xFFFFFFFFu, base, leader);
            if (pq) {
                int pos = base + __popc(msk & ((1u << lane) - 1u));
                if (pos < CAP)
                    g_cand[(i * 2 + 1) * CAP + pos] =
                        ((ull)u4[q] << 32) | (unsigned)(~(unsigned)(mb + q));
            }
        }
    }
    __syncthreads();

    const int nf = s_nflag;
    const int wid = t >> 5;
    for (int e = wid; e < nf; e += 8) {
        const int m = s_flag[e];
        float4 p = (m < NPROP) ? proposals[(size_t)i * NPROP + m] : s_gt[m - NPROP];
        const float ab = __fmul_rn(__fsub_rn(p.z, p.x), __fsub_rn(p.w, p.y));

        float bi, bd; int bj;
        {
            float4 g = s_gt[lane];
            float wx = __fsub_rn(fminf(g.z, p.z), fmaxf(g.x, p.x));
            float hy = __fsub_rn(fminf(g.w, p.w), fmaxf(g.y, p.y));
            bi = __fmul_rn(fmaxf(wx, 0.0f), fmaxf(hy, 0.0f));
            bd = __fsub_rn(__fadd_rn(s_area[lane], ab), bi);
            bj = lane;
        }
        #pragma unroll
        for (int kk = 1; kk < 4; kk++) {
            int j = lane + kk * 32;
            float4 g = s_gt[j];
            float wx = __fsub_rn(fminf(g.z, p.z), fmaxf(g.x, p.x));
            float hy = __fsub_rn(fminf(g.w, p.w), fmaxf(g.y, p.y));
            float inter = __fmul_rn(fmaxf(wx, 0.0f), fmaxf(hy, 0.0f));
            float den = __fsub_rn(__fadd_rn(s_area[j], ab), inter);
            float u = __fmul_rn(inter, bd), v = __fmul_rn(bi, den);
            float eu = __fmaf_rn(inter, bd, -u), ev = __fmaf_rn(bi, den, -v);
            if ((u > v) || (u == v && eu > ev)) { bi = inter; bd = den; bj = j; }
        }
        #pragma unroll
        for (int off = 16; off > 0; off >>= 1) {
            float obi = __shfl_xor_sync(0xFFFFFFFFu, bi, off);
            float obd = __shfl_xor_sync(0xFFFFFFFFu, bd, off);
            int   obj = __shfl_xor_sync(0xFFFFFFFFu, bj, off);
            float u = __fmul_rn(obi, bd), v = __fmul_rn(bi, obd);
            float eu = __fmaf_rn(obi, bd, -u), ev = __fmaf_rn(bi, obd, -v);
            bool gt = (u > v) || (u == v && eu > ev);
            bool eq = (u == v) && (eu == ev);
            if (gt || (eq && obj < bj)) { bi = obi; bd = obd; bj = obj; }
        }
        if (lane == 0) {
            bool pos = __fdiv_rn(bi, bd) >= 0.5f;     // bit-exact threshold
            unsigned u = rscore_u((unsigned)(gi + m));
            g_rec[gi + m] = (u << 1) | (pos ? 1u : 0u);
            if (pos) {
                g_labcl[gi + m] = s_lab[bj] | (bj << 8);
                int p2 = atomicAdd(&g_ccnt[i * 2 + 0], 1);
                if (p2 < CAP)
                    g_cand[(i * 2 + 0) * CAP + p2] = ((ull)u << 32) | (unsigned)(~(unsigned)m);
            } else if (u >= TNEG) {
                int p2 = atomicAdd(&g_ccnt[i * 2 + 1], 1);
                if (p2 < CAP)
                    g_cand[(i * 2 + 1) * CAP + p2] = ((ull)u << 32) | (unsigned)(~(unsigned)m);
            }
        }
    }
}

// ---------------- kernel B: load + histogram threshold + tight rank sort + encode ----------------
__global__ void __launch_bounds__(1024) select_kernel(
        const float4* __restrict__ proposals,
        const float4* __restrict__ gt_boxes,
        float* __restrict__ out) {
    __shared__ ull cand[CAP];        // 16KB (also reused by fallback)
    __shared__ ull cand2[CAP2];      // 8KB
    __shared__ int hist[NBIN];       // 8KB
    __shared__ int csum[1024];       // 4KB
    __shared__ int c2r[32];
    __shared__ int s_red[32];
    __shared__ int s_bc, s_cc, s_B, s_cnt2;

    const int i = blockIdx.x;
    const int cat = blockIdx.y;
    const unsigned want = cat ? 0u : 1u;
    const int k = cat ? KNEG : KPOS;
    const int t = threadIdx.x;
    const int lane = t & 31, wid = t >> 5;

    const unsigned T_lo = cat ? TNEG : 0u;
    const int shift = cat ? 8 : 12;          // 2048 bins over the candidate u-range

    #pragma unroll
    for (int b = 0; b < NBIN / 1024; b++) hist[t + b * 1024] = 0;
    if (t == 0) { s_cnt2 = 0; s_cc = 0; }
    __syncthreads();

    const int cnt = g_ccnt[i * 2 + cat];
    int CC;
    if (cnt >= k && cnt <= CAP) {
        // fast path: load candidates + histogram their u values
        for (int c = t; c < cnt; c += 1024) {
            ull key = g_cand[(i * 2 + cat) * CAP + c];
            cand[c] = key;
            unsigned u = (unsigned)(key >> 32);
            atomicAdd(&hist[(u - T_lo) >> shift], 1);
        }
        CC = cnt;
        __syncthreads();
    } else {
        // exact fallback over g_rec (statistically never taken)
        const unsigned* __restrict__ rec = g_rec + (size_t)i * M_TOT;
        unsigned lo = 0, hi = 8388607u;
        while (lo < hi) {
            unsigned mid = (lo + hi + 1) >> 1;
            int c = 0;
            for (int m = t; m < M_TOT; m += 1024) {
                unsigned r = rec[m];
                c += ((r & 1u) == want && (r >> 1) >= mid);
            }
            #pragma unroll
            for (int o = 16; o > 0; o >>= 1) c += __shfl_xor_sync(0xFFFFFFFFu, c, o);
            if (lane == 0) s_red[wid] = c;
            __syncthreads();
            if (t == 0) { int s = 0; for (int w = 0; w < 32; w++) s += s_red[w]; s_bc = s; }
            __syncthreads();
            if (s_bc >= k) lo = mid; else hi = mid - 1;
            __syncthreads();
        }
        for (int m = t; m < M_TOT; m += 1024) {
            unsigned r = rec[m];
            if ((r & 1u) == want && (r >> 1) >= lo) {
                int p = atomicAdd(&s_cc, 1);
                if (p < CAP)
                    cand[p] = ((ull)(r >> 1) << 32) | (unsigned)(~(unsigned)m);
            }
        }
        __syncthreads();
        CC = min(s_cc, CAP);
        for (int c = t; c < CC; c += 1024) {
            unsigned u = (unsigned)(cand[c] >> 32);
            int b = (int)((u - T_lo) >> shift);
            b = min(max(b, 0), NBIN - 1);
            atomicAdd(&hist[b], 1);
        }
        __syncthreads();
    }

    // ---- find exact top-k bucket threshold ----
    csum[t] = hist[t * 2] + hist[t * 2 + 1];
    __syncthreads();
    if (t < 32) {
        int s = 0;
        #pragma unroll
        for (int b = 0; b < 32; b++) s += csum[t * 32 + b];
        c2r[t] = s;
    }
    __syncthreads();
    if (t == 0) {
        int acc = 0;
        int cc = 31;
        for (; cc > 0; cc--) { if (acc + c2r[cc] >= k) break; acc += c2r[cc]; }
        int tt = cc * 32 + 31;
        for (; tt > cc * 32; tt--) { if (acc + csum[tt] >= k) break; acc += csum[tt]; }
        int b = tt * 2 + 1;
        for (; b > tt * 2; b--) { if (acc + hist[b] >= k) break; acc += hist[b]; }
        s_B = b;
    }
    __syncthreads();
    const unsigned T = T_lo + ((unsigned)s_B << shift);

    // ---- compact to refined set: CC2 in [k, k + binload] ----
    for (int c = t; c < CC; c += 1024) {
        ull key = cand[c];
        if ((unsigned)(key >> 32) >= T) {
            int pos = atomicAdd(&s_cnt2, 1);
            if (pos < CAP2) cand2[pos] = key;
        }
    }
    __syncthreads();

    // overflow guard (statistically never): rank over the full candidate set
    const ull* sel = (s_cnt2 <= CAP2) ? cand2 : cand;
    const int CN = (s_cnt2 <= CAP2) ? s_cnt2 : CC;

    // ---- rank-counting sort (distinct (u,~m) keys) + fused encode ----
    for (int c = t; c < CN; c += 1024) {
        const ull mykey = sel[c];
        int rnk = 0;
        for (int j = 0; j < CN; j++) rnk += (sel[j] > mykey);
        if (rnk < k) {
            int m = (int)(~(unsigned)(mykey & 0xFFFFFFFFULL));
            int label = 0, cl = 0;
            if (cat == 0) {
                int labcl = g_labcl[(size_t)i * M_TOT + m];
                label = labcl & 0xFF;
                cl = labcl >> 8;
            }
            float4 p = (m < NPROP) ? proposals[(size_t)i * NPROP + m]
                                   : gt_boxes[i * NGT + (m - NPROP)];
            float4 g = gt_boxes[i * NGT + cl];

            float rw = p.z - p.x, rh = p.w - p.y;
            float rcx = p.x + 0.5f * rw, rcy = p.y + 0.5f * rh;
            float gw = g.z - g.x, gh = g.w - g.y;
            float gcx = g.x + 0.5f * gw, gcy = g.y + 0.5f * gh;

            float t0 = 10.0f * __fdiv_rn(gcx - rcx, rw);
            float t1 = 10.0f * __fdiv_rn(gcy - rcy, rh);
            float t2 = 5.0f * logf(__fdiv_rn(gw, rw));
            float t3 = 5.0f * logf(__fdiv_rn(gh, rh));

            int row = i * NSAMP + (cat ? KPOS : 0) + rnk;
            out[row * 4 + 0] = t0;
            out[row * 4 + 1] = t1;
            out[row * 4 + 2] = t2;
            out[row * 4 + 3] = t3;
            out[NIMG * NSAMP * 4 + row] = (float)label;
            out[NIMG * NSAMP * 4 + NIMG * NSAMP + row] = (float)m;
        }
    }
    __syncthreads();
    if (t == 0) g_ccnt[i * 2 + cat] = 0;   // invariant for next graph replay
}

// ---------------- launch ----------------
extern "C" void kernel_launch(void* const* d_in, const int* in_sizes, int n_in,
                              void* d_out, int out_size) {
    const float4* proposals = (const float4*)d_in[0];
    const float4* gt_boxes  = (const float4*)d_in[1];
    const int*    gt_labels = (const int*)d_in[2];
    float* out = (float*)d_out;

    prep_kernel<<<dim3((M_TOT + 1023) / 1024, NIMG), 256>>>(proposals, gt_boxes, gt_labels);
    select_kernel<<<dim3(NIMG, 2), 1024>>>(proposals, gt_boxes, out);
}

// round 11
// speedup vs baseline: 2.3575x; 1.2405x over previous
#include <cuda_runtime.h>
#include <cstdint>
#include <math.h>

#define NIMG 16
#define NPROP 16384
#define NGT 128
#define M_TOT 16512           // NPROP + NGT
#define KPOS 128
#define KNEG 384
#define NSAMP 512
#define CAP 2048              // per (img, cat) candidate capacity
#define CAP2 1024             // refined candidate capacity
#define NBIN 2048
#define TNEG 7864320u         // 2^23 - 2^19 : neg score window

typedef unsigned long long ull;

// ---------------- scratch (zero-initialized at module load) ----------------
__device__ unsigned g_rec[NIMG * M_TOT];     // (u23<<1)|is_pos  (fallback only)
__device__ int g_labcl[NIMG * M_TOT];        // label|(cl<<8)    (positives)
__device__ ull g_cand[NIMG * 2 * CAP];
__device__ int g_ccnt[NIMG * 2];             // reset by select at end of each run

// ---------------- threefry2x32 (jax partitionable path) ----------------
__device__ __forceinline__ unsigned rscore_u(unsigned f) {
    unsigned k0 = 0u, k1 = 42u;
    unsigned ks2 = k0 ^ k1 ^ 0x1BD11BDAu;
    unsigned x0 = 0u, x1 = f;
    x0 += k0; x1 += k1;
#define TF_R(r) { x0 += x1; x1 = (x1 << (r)) | (x1 >> (32 - (r))); x1 ^= x0; }
    TF_R(13) TF_R(15) TF_R(26) TF_R(6)
    x0 += k1; x1 += ks2 + 1u;
    TF_R(17) TF_R(29) TF_R(16) TF_R(24)
    x0 += ks2; x1 += k0 + 2u;
    TF_R(13) TF_R(15) TF_R(26) TF_R(6)
    x0 += k0; x1 += k1 + 3u;
    TF_R(17) TF_R(29) TF_R(16) TF_R(24)
    x0 += k1; x1 += ks2 + 4u;
    TF_R(13) TF_R(15) TF_R(26) TF_R(6)
    x0 += ks2; x1 += k0 + 5u;
#undef TF_R
    return (x0 ^ x1) >> 9;   // 23-bit uniform; score = u * 2^-23 (monotone)
}

// ---------------- kernel A: uniform 4-ILP screen + redo + append ----------------
__global__ void __launch_bounds__(512) prep_kernel(
        const float4* __restrict__ proposals,
        const float4* __restrict__ gt_boxes,
        const int* __restrict__ gt_labels) {
    __shared__ float4 s_gt[NGT];
    __shared__ float  s_area[NGT];
    __shared__ float  s_sa3[NGT];
    __shared__ int    s_lab[NGT];
    __shared__ int    s_flag[512];
    __shared__ int    s_nflag;

    const int i = blockIdx.y;
    const int t = threadIdx.x;
    const int lane = t & 31;
    if (t == 0) s_nflag = 0;
    if (t < NGT) {
        float4 g = gt_boxes[i * NGT + t];
        s_gt[t] = g;
        float a = __fmul_rn(__fsub_rn(g.z, g.x), __fsub_rn(g.w, g.y));
        s_area[t] = a;
        s_sa3[t] = a * (1.0f / 3.0f);
        s_lab[t] = gt_labels[i * NGT + t];
    }
    __syncthreads();

    const int gi = i * M_TOT;
    const int m = blockIdx.x * 512 + t;
    const bool valid = (m < M_TOT);
    unsigned u = 0u;
    bool flg = false;

    if (valid) {
        float4 p = (m < NPROP) ? proposals[(size_t)i * NPROP + m] : s_gt[m - NPROP];
        const float ab3 = __fmul_rn(__fmul_rn(__fsub_rn(p.z, p.x), __fsub_rn(p.w, p.y)),
                                    (1.0f / 3.0f));
        // 4 independent accumulator chains over uniform (broadcast) GT loop
        float a0 = -1e30f, a1 = -1e30f, a2 = -1e30f, a3 = -1e30f;
        #pragma unroll 4
        for (int j = 0; j < NGT; j += 4) {
            {
                float4 g = s_gt[j + 0];
                float wx = fmaxf(__fsub_rn(fminf(g.z, p.z), fmaxf(g.x, p.x)), 0.0f);
                float hy = __fsub_rn(fminf(g.w, p.w), fmaxf(g.y, p.y));
                a0 = fmaxf(a0, __fmaf_rn(wx, hy, -s_sa3[j + 0]));
            }
            {
                float4 g = s_gt[j + 1];
                float wx = fmaxf(__fsub_rn(fminf(g.z, p.z), fmaxf(g.x, p.x)), 0.0f);
                float hy = __fsub_rn(fminf(g.w, p.w), fmaxf(g.y, p.y));
                a1 = fmaxf(a1, __fmaf_rn(wx, hy, -s_sa3[j + 1]));
            }
            {
                float4 g = s_gt[j + 2];
                float wx = fmaxf(__fsub_rn(fminf(g.z, p.z), fmaxf(g.x, p.x)), 0.0f);
                float hy = __fsub_rn(fminf(g.w, p.w), fmaxf(g.y, p.y));
                a2 = fmaxf(a2, __fmaf_rn(wx, hy, -s_sa3[j + 2]));
            }
            {
                float4 g = s_gt[j + 3];
                float wx = fmaxf(__fsub_rn(fminf(g.z, p.z), fmaxf(g.x, p.x)), 0.0f);
                float hy = __fsub_rn(fminf(g.w, p.w), fmaxf(g.y, p.y));
                a3 = fmaxf(a3, __fmaf_rn(wx, hy, -s_sa3[j + 3]));
            }
        }
        float acc = fmaxf(fmaxf(a0, a1), fmaxf(a2, a3));
        // flag iff possibly max-IoU >= 0.5 (margin 1.0 >> fp error; superset-safe)
        flg = (acc >= ab3 - 1.0f);
        u = rscore_u((unsigned)(gi + m));
        g_rec[gi + m] = u << 1;                     // default: negative
        if (flg) { int pp = atomicAdd(&s_nflag, 1); s_flag[pp] = m; }
    }

    // negative candidate append (unflagged, windowed) — warp-aggregated
    {
        bool pq = valid && !flg && (u >= TNEG);
        unsigned msk = __ballot_sync(0xFFFFFFFFu, pq);
        if (msk) {
            int leader = __ffs(msk) - 1;
            int base = 0;
            if (lane == leader) base = atomicAdd(&g_ccnt[i * 2 + 1], __popc(msk));
            base = __shfl_sync(0xFFFFFFFFu, base, leader);
            if (pq) {
                int pos = base + __popc(msk & ((1u << lane) - 1u));
                if (pos < CAP)
                    g_cand[(i * 2 + 1) * CAP + pos] =
                        ((ull)u << 32) | (unsigned)(~(unsigned)m);
            }
        }
    }
    __syncthreads();

    // ---- exact redo: one warp per flagged proposal (validated path) ----
    const int nf = s_nflag;
    const int wid = t >> 5;
    for (int e = wid; e < nf; e += 16) {
        const int mm = s_flag[e];
        float4 p = (mm < NPROP) ? proposals[(size_t)i * NPROP + mm] : s_gt[mm - NPROP];
        const float ab = __fmul_rn(__fsub_rn(p.z, p.x), __fsub_rn(p.w, p.y));

        float bi, bd; int bj;
        {
            float4 g = s_gt[lane];
            float wx = __fsub_rn(fminf(g.z, p.z), fmaxf(g.x, p.x));
            float hy = __fsub_rn(fminf(g.w, p.w), fmaxf(g.y, p.y));
            bi = __fmul_rn(fmaxf(wx, 0.0f), fmaxf(hy, 0.0f));
            bd = __fsub_rn(__fadd_rn(s_area[lane], ab), bi);
            bj = lane;
        }
        #pragma unroll
        for (int kk = 1; kk < 4; kk++) {
            int j = lane + kk * 32;
            float4 g = s_gt[j];
            float wx = __fsub_rn(fminf(g.z, p.z), fmaxf(g.x, p.x));
            float hy = __fsub_rn(fminf(g.w, p.w), fmaxf(g.y, p.y));
            float inter = __fmul_rn(fmaxf(wx, 0.0f), fmaxf(hy, 0.0f));
            float den = __fsub_rn(__fadd_rn(s_area[j], ab), inter);
            float uu = __fmul_rn(inter, bd), v = __fmul_rn(bi, den);
            float eu = __fmaf_rn(inter, bd, -uu), ev = __fmaf_rn(bi, den, -v);
            if ((uu > v) || (uu == v && eu > ev)) { bi = inter; bd = den; bj = j; }
        }
        #pragma unroll
        for (int off = 16; off > 0; off >>= 1) {
            float obi = __shfl_xor_sync(0xFFFFFFFFu, bi, off);
            float obd = __shfl_xor_sync(0xFFFFFFFFu, bd, off);
            int   obj = __shfl_xor_sync(0xFFFFFFFFu, bj, off);
            float uu = __fmul_rn(obi, bd), v = __fmul_rn(bi, obd);
            float eu = __fmaf_rn(obi, bd, -uu), ev = __fmaf_rn(bi, obd, -v);
            bool gt = (uu > v) || (uu == v && eu > ev);
            bool eq = (uu == v) && (eu == ev);
            if (gt || (eq && obj < bj)) { bi = obi; bd = obd; bj = obj; }
        }
        if (lane == 0) {
            bool pos = __fdiv_rn(bi, bd) >= 0.5f;     // bit-exact threshold
            unsigned uu = rscore_u((unsigned)(gi + mm));
            g_rec[gi + mm] = (uu << 1) | (pos ? 1u : 0u);
            if (pos) {
                g_labcl[gi + mm] = s_lab[bj] | (bj << 8);
                int p2 = atomicAdd(&g_ccnt[i * 2 + 0], 1);
                if (p2 < CAP)
                    g_cand[(i * 2 + 0) * CAP + p2] = ((ull)uu << 32) | (unsigned)(~(unsigned)mm);
            } else if (uu >= TNEG) {
                int p2 = atomicAdd(&g_ccnt[i * 2 + 1], 1);
                if (p2 < CAP)
                    g_cand[(i * 2 + 1) * CAP + p2] = ((ull)uu << 32) | (unsigned)(~(unsigned)mm);
            }
        }
    }
}

// ---------------- kernel B: load + histogram threshold + tight rank sort + encode ----------------
__global__ void __launch_bounds__(1024) select_kernel(
        const float4* __restrict__ proposals,
        const float4* __restrict__ gt_boxes,
        float* __restrict__ out) {
    __shared__ ull cand[CAP];        // 16KB (also reused by fallback)
    __shared__ ull cand2[CAP2];      // 8KB
    __shared__ int hist[NBIN];       // 8KB
    __shared__ int csum[1024];       // 4KB
    __shared__ int c2r[32];
    __shared__ int s_red[32];
    __shared__ int s_bc, s_cc, s_B, s_cnt2;

    const int i = blockIdx.x;
    const int cat = blockIdx.y;
    const unsigned want = cat ? 0u : 1u;
    const int k = cat ? KNEG : KPOS;
    const int t = threadIdx.x;
    const int lane = t & 31, wid = t >> 5;

    const unsigned T_lo = cat ? TNEG : 0u;
    const int shift = cat ? 8 : 12;          // 2048 bins over the candidate u-range

    #pragma unroll
    for (int b = 0; b < NBIN / 1024; b++) hist[t + b * 1024] = 0;
    if (t == 0) { s_cnt2 = 0; s_cc = 0; }
    __syncthreads();

    const int cnt = g_ccnt[i * 2 + cat];
    int CC;
    if (cnt >= k && cnt <= CAP) {
        for (int c = t; c < cnt; c += 1024) {
            ull key = g_cand[(i * 2 + cat) * CAP + c];
            cand[c] = key;
            unsigned u = (unsigned)(key >> 32);
            atomicAdd(&hist[(u - T_lo) >> shift], 1);
        }
        CC = cnt;
        __syncthreads();
    } else {
        // exact fallback over g_rec (statistically never taken)
        const unsigned* __restrict__ rec = g_rec + (size_t)i * M_TOT;
        unsigned lo = 0, hi = 8388607u;
        while (lo < hi) {
            unsigned mid = (lo + hi + 1) >> 1;
            int c = 0;
            for (int m = t; m < M_TOT; m += 1024) {
                unsigned r = rec[m];
                c += ((r & 1u) == want && (r >> 1) >= mid);
            }
            #pragma unroll
            for (int o = 16; o > 0; o >>= 1) c += __shfl_xor_sync(0xFFFFFFFFu, c, o);
            if (lane == 0) s_red[wid] = c;
            __syncthreads();
            if (t == 0) { int s = 0; for (int w = 0; w < 32; w++) s += s_red[w]; s_bc = s; }
            __syncthreads();
            if (s_bc >= k) lo = mid; else hi = mid - 1;
            __syncthreads();
        }
        for (int m = t; m < M_TOT; m += 1024) {
            unsigned r = rec[m];
            if ((r & 1u) == want && (r >> 1) >= lo) {
                int p = atomicAdd(&s_cc, 1);
                if (p < CAP)
                    cand[p] = ((ull)(r >> 1) << 32) | (unsigned)(~(unsigned)m);
            }
        }
        __syncthreads();
        CC = min(s_cc, CAP);
        for (int c = t; c < CC; c += 1024) {
            unsigned u = (unsigned)(cand[c] >> 32);
            int b = (int)((u - T_lo) >> shift);
            b = min(max(b, 0), NBIN - 1);
            atomicAdd(&hist[b], 1);
        }
        __syncthreads();
    }

    // ---- find exact top-k bucket threshold ----
    csum[t] = hist[t * 2] + hist[t * 2 + 1];
    __syncthreads();
    if (t < 32) {
        int s = 0;
        #pragma unroll
        for (int b = 0; b < 32; b++) s += csum[t * 32 + b];
        c2r[t] = s;
    }
    __syncthreads();
    if (t == 0) {
        int acc = 0;
        int cc = 31;
        for (; cc > 0; cc--) { if (acc + c2r[cc] >= k) break; acc += c2r[cc]; }
        int tt = cc * 32 + 31;
        for (; tt > cc * 32; tt--) { if (acc + csum[tt] >= k) break; acc += csum[tt]; }
        int b = tt * 2 + 1;
        for (; b > tt * 2; b--) { if (acc + hist[b] >= k) break; acc += hist[b]; }
        s_B = b;
    }
    __syncthreads();
    const unsigned T = T_lo + ((unsigned)s_B << shift);

    // ---- compact to refined set: CC2 in [k, k + binload] ----
    for (int c = t; c < CC; c += 1024) {
        ull key = cand[c];
        if ((unsigned)(key >> 32) >= T) {
            int pos = atomicAdd(&s_cnt2, 1);
            if (pos < CAP2) cand2[pos] = key;
        }
    }
    __syncthreads();

    const ull* sel = (s_cnt2 <= CAP2) ? cand2 : cand;
    const int CN = (s_cnt2 <= CAP2) ? s_cnt2 : CC;

    // ---- rank-counting sort (distinct (u,~m) keys) + fused encode ----
    for (int c = t; c < CN; c += 1024) {
        const ull mykey = sel[c];
        int rnk = 0;
        for (int j = 0; j < CN; j++) rnk += (sel[j] > mykey);
        if (rnk < k) {
            int m = (int)(~(unsigned)(mykey & 0xFFFFFFFFULL));
            int label = 0, cl = 0;
            if (cat == 0) {
                int labcl = g_labcl[(size_t)i * M_TOT + m];
                label = labcl & 0xFF;
                cl = labcl >> 8;
            }
            float4 p = (m < NPROP) ? proposals[(size_t)i * NPROP + m]
                                   : gt_boxes[i * NGT + (m - NPROP)];
            float4 g = gt_boxes[i * NGT + cl];

            float rw = p.z - p.x, rh = p.w - p.y;
            float rcx = p.x + 0.5f * rw, rcy = p.y + 0.5f * rh;
            float gw = g.z - g.x, gh = g.w - g.y;
            float gcx = g.x + 0.5f * gw, gcy = g.y + 0.5f * gh;

            float t0 = 10.0f * __fdiv_rn(gcx - rcx, rw);
            float t1 = 10.0f * __fdiv_rn(gcy - rcy, rh);
            float t2 = 5.0f * logf(__fdiv_rn(gw, rw));
            float t3 = 5.0f * logf(__fdiv_rn(gh, rh));

            int row = i * NSAMP + (cat ? KPOS : 0) + rnk;
            out[row * 4 + 0] = t0;
            out[row * 4 + 1] = t1;
            out[row * 4 + 2] = t2;
            out[row * 4 + 3] = t3;
            out[NIMG * NSAMP * 4 + row] = (float)label;
            out[NIMG * NSAMP * 4 + NIMG * NSAMP + row] = (float)m;
        }
    }
    __syncthreads();
    if (t == 0) g_ccnt[i * 2 + cat] = 0;   // invariant for next graph replay
}

// ---------------- launch ----------------
extern "C" void kernel_launch(void* const* d_in, const int* in_sizes, int n_in,
                              void* d_out, int out_size) {
    const float4* proposals = (const float4*)d_in[0];
    const float4* gt_boxes  = (const float4*)d_in[1];
    const int*    gt_labels = (const int*)d_in[2];
    float* out = (float*)d_out;

    prep_kernel<<<dim3((M_TOT + 511) / 512, NIMG), 512>>>(proposals, gt_boxes, gt_labels);
    select_kernel<<<dim3(NIMG, 2), 1024>>>(proposals, gt_boxes, out);
}